// round 11
// baseline (speedup 1.0000x reference)
#include <cuda_runtime.h>

// SSIM over (64,1,512,512) f32, 11x11 zero-padded box filters.
// Separable box filter, R9 resubmission (R10 was an infra failure, no data):
//   - R7 base: float4-packed staging (sx, sy, s(x^2+y^2), s(x*y)), RCHUNK=8,
//     RBLOCK=64, double-buffered `so`, 2 syncs/chunk, store pass of chunk
//     ck-1 overlapped under V(ck)'s LDGs, staged fully-coalesced stores.
//   - Single delta vs 70.1us baseline: __launch_bounds__(128,8) to admit an
//     8th CTA/SM (R5 proved 64 regs achievable for this body) + 32-bit
//     offset arithmetic to help the register allocator.

namespace {
constexpr int W = 512, H = 512;
constexpr int PAD = 5;                 // win=11 -> halo 5
constexpr int TX = 118;                // output cols per strip
constexpr int NSTRIP = 5;              // ceil(512/118)
constexpr int THREADS = 128;           // TX + 2*PAD
constexpr int RCHUNK = 8;              // rows staged in smem per iteration
constexpr int RBLOCK = 64;             // output rows per CTA
constexpr int NCHUNK = RBLOCK / RCHUNK;
constexpr int PITCH = 129;             // vs pitch (float4s per row), conflict-free
constexpr int SO_PITCH = 119;          // staging pitch (conflict-free vs (hrow,hch))
constexpr float INV_N = 1.0f / 121.0f;
constexpr float COV = 121.0f / 120.0f;
}

__device__ __forceinline__ float ld0(const float* __restrict__ p, int r, int gcol, bool cv) {
    if (cv && r >= 0 && r < H) return __ldg(p + r * W + gcol);
    return 0.0f;
}

__global__ __launch_bounds__(THREADS, 8) void ssim_kernel(
    const float* __restrict__ img, const float* __restrict__ ref,
    const float* __restrict__ drange, float* __restrict__ out)
{
    __shared__ float4 vs4[RCHUNK][PITCH];       // (sx, sy, s(xx+yy), sxy)
    __shared__ float  so[2][RCHUNK][SO_PITCH];  // double-buffered staging tile

    const int tid   = threadIdx.x;
    const int strip = blockIdx.x;
    const int rb    = blockIdx.y;
    const int b     = blockIdx.z;

    const int ib = b * (H * W);                  // 32-bit image offset (<2^26)
    const float* ip = img + ib;
    const float* rp = ref + ib;
    float*       op = out + ib;

    const float dr = __ldg(drange + b);
    const float C1 = (0.01f * dr) * (0.01f * dr);
    const float C2 = (0.03f * dr) * (0.03f * dr);

    const int  gcol = strip * TX + tid - PAD;       // column this thread streams
    const bool cv   = (gcol >= 0) && (gcol < W);

    const int r_start = rb * RBLOCK;

    // --- init vertical running sums: rows [r_start-5, r_start+5] ---
    float sx = 0.f, sy = 0.f, sq = 0.f, sxy = 0.f;
    #pragma unroll
    for (int d = -PAD; d <= PAD; ++d) {
        float x = ld0(ip, r_start + d, gcol, cv);
        float y = ld0(rp, r_start + d, gcol, cv);
        sx += x; sy += y;
        sq  = fmaf(x, x, sq);
        sq  = fmaf(y, y, sq);
        sxy = fmaf(x, y, sxy);
    }

    const int hrow = tid & (RCHUNK - 1);   // 0..7
    const int hch  = tid >> 3;             // 0..15
    const int c0   = hch * 8;              // 15 chunks of 8 cover 118 (hch=15 idle)
    const bool hact = (c0 < TX);

    const int  ocol   = strip * TX + tid;  // store-pass column for this thread
    const bool st_act = (tid < TX) && (ocol < W);

    for (int ck = 0; ck < NCHUNK; ++ck) {
        const int r0 = r_start + ck * RCHUNK;

        // --- V(ck): stage 8 rows of packed vertical sums (LDGs issue first) ---
        #pragma unroll
        for (int i = 0; i < RCHUNK; ++i) {
            vs4[i][tid] = make_float4(sx, sy, sq, sxy);
            const int r = r0 + i;
            float xn = ld0(ip, r + PAD + 1, gcol, cv);
            float yn = ld0(rp, r + PAD + 1, gcol, cv);
            float xo = ld0(ip, r - PAD, gcol, cv);        // L1/L2 hit (loaded 11 rows ago)
            float yo = ld0(rp, r - PAD, gcol, cv);
            sx += xn - xo;
            sy += yn - yo;
            sq  += (xn * xn + yn * yn) - (xo * xo + yo * yo);
            sxy += xn * yn - xo * yo;
        }

        // --- S(ck-1): coalesced store pass, overlapped under V's LDG latency ---
        if (ck > 0 && st_act) {
            float* o = op + (r_start + (ck - 1) * RCHUNK) * W + ocol;
            const float (* __restrict__ sp)[SO_PITCH] = so[(ck - 1) & 1];
            #pragma unroll
            for (int rr = 0; rr < RCHUNK; ++rr) { *o = sp[rr][tid]; o += W; }
        }
        __syncthreads();   // vs4 RAW (V->H); also orders S(ck-1) before H(ck)

        // --- H(ck): horizontal sliding sums + SSIM -> so[ck&1] ---
        if (hact) {
            float (* __restrict__ sw)[SO_PITCH] = so[ck & 1];
            float hx = 0.f, hy = 0.f, hq = 0.f, hxy = 0.f;
            #pragma unroll
            for (int j = 0; j < 11; ++j) {
                float4 v = vs4[hrow][c0 + j];
                hx += v.x; hy += v.y; hq += v.z; hxy += v.w;
            }
            #pragma unroll
            for (int k = 0; k < 8; ++k) {
                const int c = c0 + k;
                if (c < TX) {
                    float ux  = hx  * INV_N;
                    float uy  = hy  * INV_N;
                    float uq  = hq  * INV_N;
                    float uxy = hxy * INV_N;
                    float uxux = ux * ux;
                    float uyuy = uy * uy;
                    float vxy = COV * (uxy - ux * uy);
                    float A1 = 2.f * ux * uy + C1;
                    float A2 = 2.f * vxy + C2;
                    float B1 = uxux + uyuy + C1;
                    float B2 = COV * (uq - uxux - uyuy) + C2;
                    sw[hrow][c] = __fdividef(A1 * A2, B1 * B2);
                    if (k < 7) {    // last slide feeds nothing
                        float4 va = vs4[hrow][c + 11];
                        float4 vb = vs4[hrow][c];
                        hx  += va.x - vb.x;
                        hy  += va.y - vb.y;
                        hq  += va.z - vb.z;
                        hxy += va.w - vb.w;
                    }
                }
            }
        }
        __syncthreads();   // so RAW (H->S next iter); vs4 WAR (H before next V)
    }

    // --- epilogue: store pass for the final chunk ---
    if (st_act) {
        float* o = op + (r_start + (NCHUNK - 1) * RCHUNK) * W + ocol;
        const float (* __restrict__ sp)[SO_PITCH] = so[(NCHUNK - 1) & 1];
        #pragma unroll
        for (int rr = 0; rr < RCHUNK; ++rr) { *o = sp[rr][tid]; o += W; }
    }
}

extern "C" void kernel_launch(void* const* d_in, const int* in_sizes, int n_in,
                              void* d_out, int out_size) {
    const float* img = (const float*)d_in[0];
    const float* ref = (const float*)d_in[1];
    const float* dr  = (const float*)d_in[2];
    float* out = (float*)d_out;
    const int B = in_sizes[2];            // batch = data_range element count (64)
    dim3 grid(NSTRIP, H / RBLOCK, B);
    ssim_kernel<<<grid, THREADS>>>(img, ref, dr, out);
}

// round 13
// speedup vs baseline: 1.3840x; 1.3840x over previous
#include <cuda_runtime.h>

// SSIM over (64,1,512,512) f32, 11x11 zero-padded box filters.
// Separable box filter, R12 revision (= R7 + register ring for old rows):
//   - R7 base: float4-packed staging, RCHUNK=8, RBLOCK=64, double-buffered
//     `so`, 2 syncs/chunk, store pass overlapped under V's LDGs.
//   - NEW: the chunk loop is FULLY UNROLLED (64 V iterations) so the 11-row
//     (x,y) ring lives in registers with static indices (slot = i mod 11).
//     The xo/yo re-loads (and their L1D-capacity dependence, shown fatal in
//     R9's 8-CTA experiment) are eliminated: V issues only 2 streaming LDGs
//     per row.
//   - +22 live regs -> __launch_bounds__(128,6): 6 CTAs/SM.

namespace {
constexpr int W = 512, H = 512;
constexpr int PAD = 5;                 // win=11 -> halo 5
constexpr int TX = 118;                // output cols per strip
constexpr int NSTRIP = 5;              // ceil(512/118)
constexpr int THREADS = 128;           // TX + 2*PAD
constexpr int RCHUNK = 8;              // rows staged in smem per iteration
constexpr int RBLOCK = 64;             // output rows per CTA
constexpr int NCHUNK = RBLOCK / RCHUNK;
constexpr int PITCH = 129;             // vs pitch (float4s per row), conflict-free
constexpr int SO_PITCH = 119;          // staging pitch (conflict-free vs (hrow,hch))
constexpr float INV_N = 1.0f / 121.0f;
constexpr float COV = 121.0f / 120.0f;
}

__device__ __forceinline__ float ld0(const float* __restrict__ p, int r, int gcol, bool cv) {
    if (cv && r >= 0 && r < H) return __ldg(p + r * W + gcol);
    return 0.0f;
}

__global__ __launch_bounds__(THREADS, 6) void ssim_kernel(
    const float* __restrict__ img, const float* __restrict__ ref,
    const float* __restrict__ drange, float* __restrict__ out)
{
    __shared__ float4 vs4[RCHUNK][PITCH];       // (sx, sy, s(xx+yy), sxy)
    __shared__ float  so[2][RCHUNK][SO_PITCH];  // double-buffered staging tile

    const int tid   = threadIdx.x;
    const int strip = blockIdx.x;
    const int rb    = blockIdx.y;
    const int b     = blockIdx.z;

    const int ib = b * (H * W);                  // 32-bit image offset (<2^26)
    const float* ip = img + ib;
    const float* rp = ref + ib;
    float*       op = out + ib;

    const float dr = __ldg(drange + b);
    const float C1 = (0.01f * dr) * (0.01f * dr);
    const float C2 = (0.03f * dr) * (0.03f * dr);

    const int  gcol = strip * TX + tid - PAD;       // column this thread streams
    const bool cv   = (gcol >= 0) && (gcol < W);

    const int r_start = rb * RBLOCK;

    // --- init: load 11-row window into the register ring + running sums ---
    // ring[j] holds (x,y) of row r_start-5+j, j = 0..10
    float rx[11], ry[11];
    float sx = 0.f, sy = 0.f, sq = 0.f, sxy = 0.f;
    #pragma unroll
    for (int j = 0; j < 11; ++j) {
        float x = ld0(ip, r_start - PAD + j, gcol, cv);
        float y = ld0(rp, r_start - PAD + j, gcol, cv);
        rx[j] = x; ry[j] = y;
        sx += x; sy += y;
        sq  = fmaf(x, x, sq);
        sq  = fmaf(y, y, sq);
        sxy = fmaf(x, y, sxy);
    }

    const int hrow = tid & (RCHUNK - 1);   // 0..7
    const int hch  = tid >> 3;             // 0..15
    const int c0   = hch * 8;              // 15 chunks of 8 cover 118 (hch=15 idle)
    const bool hact = (c0 < TX);

    const int  ocol   = strip * TX + tid;  // store-pass column for this thread
    const bool st_act = (tid < TX) && (ocol < W);

    #pragma unroll
    for (int ck = 0; ck < NCHUNK; ++ck) {
        const int r0 = r_start + ck * RCHUNK;

        // --- V(ck): stage 8 rows; old values come from the register ring ---
        #pragma unroll
        for (int ii = 0; ii < RCHUNK; ++ii) {
            vs4[ii][tid] = make_float4(sx, sy, sq, sxy);
            const int i = ck * RCHUNK + ii;       // compile-time (full unroll)
            const int slot = i % 11;              // static ring index
            float xn = ld0(ip, r0 + ii + PAD + 1, gcol, cv);
            float yn = ld0(rp, r0 + ii + PAD + 1, gcol, cv);
            float xo = rx[slot];
            float yo = ry[slot];
            sx += xn - xo;
            sy += yn - yo;
            sq  += (xn * xn + yn * yn) - (xo * xo + yo * yo);
            sxy += xn * yn - xo * yo;
            rx[slot] = xn; ry[slot] = yn;
        }

        // --- S(ck-1): coalesced store pass, overlapped under V's LDG latency ---
        if (ck > 0 && st_act) {
            float* o = op + (r_start + (ck - 1) * RCHUNK) * W + ocol;
            const float (* __restrict__ sp)[SO_PITCH] = so[(ck - 1) & 1];
            #pragma unroll
            for (int rr = 0; rr < RCHUNK; ++rr) { *o = sp[rr][tid]; o += W; }
        }
        __syncthreads();   // vs4 RAW (V->H); also orders S(ck-1) before H(ck)

        // --- H(ck): horizontal sliding sums + SSIM -> so[ck&1] ---
        if (hact) {
            float (* __restrict__ sw)[SO_PITCH] = so[ck & 1];
            float hx = 0.f, hy = 0.f, hq = 0.f, hxy = 0.f;
            #pragma unroll
            for (int j = 0; j < 11; ++j) {
                float4 v = vs4[hrow][c0 + j];
                hx += v.x; hy += v.y; hq += v.z; hxy += v.w;
            }
            #pragma unroll
            for (int k = 0; k < 8; ++k) {
                const int c = c0 + k;
                if (c < TX) {
                    float ux  = hx  * INV_N;
                    float uy  = hy  * INV_N;
                    float uq  = hq  * INV_N;
                    float uxy = hxy * INV_N;
                    float uxux = ux * ux;
                    float uyuy = uy * uy;
                    float vxy = COV * (uxy - ux * uy);
                    float A1 = 2.f * ux * uy + C1;
                    float A2 = 2.f * vxy + C2;
                    float B1 = uxux + uyuy + C1;
                    float B2 = COV * (uq - uxux - uyuy) + C2;
                    sw[hrow][c] = __fdividef(A1 * A2, B1 * B2);
                    if (k < 7) {    // last slide feeds nothing
                        float4 va = vs4[hrow][c + 11];
                        float4 vb = vs4[hrow][c];
                        hx  += va.x - vb.x;
                        hy  += va.y - vb.y;
                        hq  += va.z - vb.z;
                        hxy += va.w - vb.w;
                    }
                }
            }
        }
        __syncthreads();   // so RAW (H->S next iter); vs4 WAR (H before next V)
    }

    // --- epilogue: store pass for the final chunk ---
    if (st_act) {
        float* o = op + (r_start + (NCHUNK - 1) * RCHUNK) * W + ocol;
        const float (* __restrict__ sp)[SO_PITCH] = so[(NCHUNK - 1) & 1];
        #pragma unroll
        for (int rr = 0; rr < RCHUNK; ++rr) { *o = sp[rr][tid]; o += W; }
    }
}

extern "C" void kernel_launch(void* const* d_in, const int* in_sizes, int n_in,
                              void* d_out, int out_size) {
    const float* img = (const float*)d_in[0];
    const float* ref = (const float*)d_in[1];
    const float* dr  = (const float*)d_in[2];
    float* out = (float*)d_out;
    const int B = in_sizes[2];            // batch = data_range element count (64)
    dim3 grid(NSTRIP, H / RBLOCK, B);
    ssim_kernel<<<grid, THREADS>>>(img, ref, dr, out);
}

// round 15
// speedup vs baseline: 1.3847x; 1.0005x over previous
#include <cuda_runtime.h>

// SSIM over (64,1,512,512) f32, 11x11 zero-padded box filters.
// Separable box filter, R14 revision (= R12 + two-chain horizontal stage):
//   - R12 base: register ring for old rows (V = 2 streaming LDGs/row), full
//     unroll, float4-packed staging, double-buffered `so`, 2 syncs/chunk,
//     store pass overlapped under V's LDGs, 6 CTAs/SM.
//   - NEW H: window A init at c0 (11 loads); window B at c0+4 derived as
//     B = A - sum v[c0..c0+3] + sum v[c0+11..c0+14]; then TWO independent
//     3-slide chains (k=0..3 and k=4..7). Distinct smem addresses drop
//     25 -> 18 per lane-chunk (slide va/vb sets are CSE'd subsets), and the
//     serial 24-add chain becomes two parallel half-chains.
//   - Chain A needs no bounds guards (c0+3 <= 115 < TX always).

namespace {
constexpr int W = 512, H = 512;
constexpr int PAD = 5;                 // win=11 -> halo 5
constexpr int TX = 118;                // output cols per strip
constexpr int NSTRIP = 5;              // ceil(512/118)
constexpr int THREADS = 128;           // TX + 2*PAD
constexpr int RCHUNK = 8;              // rows staged in smem per iteration
constexpr int RBLOCK = 64;             // output rows per CTA
constexpr int NCHUNK = RBLOCK / RCHUNK;
constexpr int PITCH = 129;             // vs pitch (float4s per row), conflict-free
constexpr int SO_PITCH = 119;          // staging pitch (conflict-free vs (hrow,hch))
constexpr float INV_N = 1.0f / 121.0f;
constexpr float COV = 121.0f / 120.0f;
}

__device__ __forceinline__ float ld0(const float* __restrict__ p, int r, int gcol, bool cv) {
    if (cv && r >= 0 && r < H) return __ldg(p + r * W + gcol);
    return 0.0f;
}

__device__ __forceinline__ float ssim_pt(float hx, float hy, float hq, float hxy,
                                         float C1, float C2) {
    float ux  = hx  * INV_N;
    float uy  = hy  * INV_N;
    float uq  = hq  * INV_N;
    float uxy = hxy * INV_N;
    float uxux = ux * ux;
    float uyuy = uy * uy;
    float vxy = COV * (uxy - ux * uy);
    float A1 = 2.f * ux * uy + C1;
    float A2 = 2.f * vxy + C2;
    float B1 = uxux + uyuy + C1;
    float B2 = COV * (uq - uxux - uyuy) + C2;
    return __fdividef(A1 * A2, B1 * B2);
}

__global__ __launch_bounds__(THREADS, 6) void ssim_kernel(
    const float* __restrict__ img, const float* __restrict__ ref,
    const float* __restrict__ drange, float* __restrict__ out)
{
    __shared__ float4 vs4[RCHUNK][PITCH];       // (sx, sy, s(xx+yy), sxy)
    __shared__ float  so[2][RCHUNK][SO_PITCH];  // double-buffered staging tile

    const int tid   = threadIdx.x;
    const int strip = blockIdx.x;
    const int rb    = blockIdx.y;
    const int b     = blockIdx.z;

    const int ib = b * (H * W);                  // 32-bit image offset (<2^26)
    const float* ip = img + ib;
    const float* rp = ref + ib;
    float*       op = out + ib;

    const float dr = __ldg(drange + b);
    const float C1 = (0.01f * dr) * (0.01f * dr);
    const float C2 = (0.03f * dr) * (0.03f * dr);

    const int  gcol = strip * TX + tid - PAD;       // column this thread streams
    const bool cv   = (gcol >= 0) && (gcol < W);

    const int r_start = rb * RBLOCK;

    // --- init: load 11-row window into the register ring + running sums ---
    float rx[11], ry[11];
    float sx = 0.f, sy = 0.f, sq = 0.f, sxy = 0.f;
    #pragma unroll
    for (int j = 0; j < 11; ++j) {
        float x = ld0(ip, r_start - PAD + j, gcol, cv);
        float y = ld0(rp, r_start - PAD + j, gcol, cv);
        rx[j] = x; ry[j] = y;
        sx += x; sy += y;
        sq  = fmaf(x, x, sq);
        sq  = fmaf(y, y, sq);
        sxy = fmaf(x, y, sxy);
    }

    const int hrow = tid & (RCHUNK - 1);   // 0..7
    const int hch  = tid >> 3;             // 0..15
    const int c0   = hch * 8;              // 15 chunks of 8 cover 118 (hch=15 idle)
    const bool hact = (c0 < TX);

    const int  ocol   = strip * TX + tid;  // store-pass column for this thread
    const bool st_act = (tid < TX) && (ocol < W);

    #pragma unroll
    for (int ck = 0; ck < NCHUNK; ++ck) {
        const int r0 = r_start + ck * RCHUNK;

        // --- V(ck): stage 8 rows; old values come from the register ring ---
        #pragma unroll
        for (int ii = 0; ii < RCHUNK; ++ii) {
            vs4[ii][tid] = make_float4(sx, sy, sq, sxy);
            const int i = ck * RCHUNK + ii;       // compile-time (full unroll)
            const int slot = i % 11;              // static ring index
            float xn = ld0(ip, r0 + ii + PAD + 1, gcol, cv);
            float yn = ld0(rp, r0 + ii + PAD + 1, gcol, cv);
            float xo = rx[slot];
            float yo = ry[slot];
            sx += xn - xo;
            sy += yn - yo;
            sq  += (xn * xn + yn * yn) - (xo * xo + yo * yo);
            sxy += xn * yn - xo * yo;
            rx[slot] = xn; ry[slot] = yn;
        }

        // --- S(ck-1): coalesced store pass, overlapped under V's LDG latency ---
        if (ck > 0 && st_act) {
            float* o = op + (r_start + (ck - 1) * RCHUNK) * W + ocol;
            const float (* __restrict__ sp)[SO_PITCH] = so[(ck - 1) & 1];
            #pragma unroll
            for (int rr = 0; rr < RCHUNK; ++rr) { *o = sp[rr][tid]; o += W; }
        }
        __syncthreads();   // vs4 RAW (V->H); also orders S(ck-1) before H(ck)

        // --- H(ck): two-chain horizontal sliding sums + SSIM -> so[ck&1] ---
        if (hact) {
            float (* __restrict__ sw)[SO_PITCH] = so[ck & 1];
            const float4* __restrict__ vrow = vs4[hrow];

            // window A: [c0, c0+10]
            float ax = 0.f, ay = 0.f, aq = 0.f, axy = 0.f;
            #pragma unroll
            for (int j = 0; j < 11; ++j) {
                float4 v = vrow[c0 + j];
                ax += v.x; ay += v.y; aq += v.z; axy += v.w;
            }
            // window B at c0+4: B = A - sum v[c0..c0+3] + sum v[c0+11..c0+14]
            float bx = ax, by = ay, bq = aq, bxy = axy;
            #pragma unroll
            for (int j = 0; j < 4; ++j) {
                float4 vm = vrow[c0 + j];
                float4 vp = vrow[c0 + 11 + j];
                bx  += vp.x - vm.x;
                by  += vp.y - vm.y;
                bq  += vp.z - vm.z;
                bxy += vp.w - vm.w;
            }

            // chain A: points c0..c0+3 (always valid: c0+3 <= 115 < TX)
            #pragma unroll
            for (int k = 0; k < 4; ++k) {
                const int c = c0 + k;
                sw[hrow][c] = ssim_pt(ax, ay, aq, axy, C1, C2);
                if (k < 3) {
                    float4 va = vrow[c + 11];
                    float4 vb = vrow[c];
                    ax += va.x - vb.x; ay += va.y - vb.y;
                    aq += va.z - vb.z; axy += va.w - vb.w;
                }
            }
            // chain B: points c0+4..c0+7 (guarded; slides only if next valid)
            #pragma unroll
            for (int k = 0; k < 4; ++k) {
                const int c = c0 + 4 + k;
                if (c < TX) {
                    sw[hrow][c] = ssim_pt(bx, by, bq, bxy, C1, C2);
                    if (k < 3 && c + 1 < TX) {
                        float4 va = vrow[c + 11];
                        float4 vb = vrow[c];
                        bx += va.x - vb.x; by += va.y - vb.y;
                        bq += va.z - vb.z; bxy += va.w - vb.w;
                    }
                }
            }
        }
        __syncthreads();   // so RAW (H->S next iter); vs4 WAR (H before next V)
    }

    // --- epilogue: store pass for the final chunk ---
    if (st_act) {
        float* o = op + (r_start + (NCHUNK - 1) * RCHUNK) * W + ocol;
        const float (* __restrict__ sp)[SO_PITCH] = so[(NCHUNK - 1) & 1];
        #pragma unroll
        for (int rr = 0; rr < RCHUNK; ++rr) { *o = sp[rr][tid]; o += W; }
    }
}

extern "C" void kernel_launch(void* const* d_in, const int* in_sizes, int n_in,
                              void* d_out, int out_size) {
    const float* img = (const float*)d_in[0];
    const float* ref = (const float*)d_in[1];
    const float* dr  = (const float*)d_in[2];
    float* out = (float*)d_out;
    const int B = in_sizes[2];            // batch = data_range element count (64)
    dim3 grid(NSTRIP, H / RBLOCK, B);
    ssim_kernel<<<grid, THREADS>>>(img, ref, dr, out);
}